// round 15
// baseline (speedup 1.0000x reference)
#include <cuda_runtime.h>
#include <math.h>
#include <stdint.h>

// ---------------- problem constants ----------------
#define BATCH   4096
#define NBLOCK  100
#define NSLOT   300
#define NYS     1236
#define HIDDIM  256
#define NSTEPS  100
#define KST     1436        // 100 + 100 + 1236
#define M5      (BATCH*5)
#define NFUSE   (NBLOCK+NSLOT) // 400
#define NEGV    (-1000.0f)

typedef unsigned long long ull;

// ---------------- scratch (device globals; no allocs allowed) ----------------
__device__ float g_xT  [(size_t)M5 * KST];
__device__ float g_act1[(size_t)M5 * 512];
__device__ float g_act2[(size_t)M5 * 512];
__device__ float g_act3[(size_t)M5 * 256];
__device__ float g_h_to[2][BATCH*HIDDIM];
__device__ float g_c_to[BATCH*HIDDIM];
__device__ float g_h_ti[2][BATCH*HIDDIM];
__device__ float g_c_ti[BATCH*HIDDIM];
__device__ float g_lto [(size_t)BATCH*NFUSE];
__device__ float g_lti [(size_t)BATCH*NBLOCK];
__device__ float g_inp [BATCH*8];
__device__ unsigned char g_mto[BATCH*NBLOCK];
__device__ unsigned char g_mti[BATCH*NBLOCK];
// SoA slot state
__device__ float g_sl0 [(size_t)BATCH*NSLOT];
__device__ float g_sw0 [(size_t)BATCH*NSLOT];
__device__ float g_scnt[(size_t)BATCH*NSLOT];
__device__ float g_WbWs[NFUSE*HIDDIM];
__device__ float g_bf  [NFUSE];
// permuted gate weights: row 4j+g (to: rows 0..1023, ti: rows 1024..2047)
__device__ float g_Wg  [2048*HIDDIM];
__device__ float g_bihp[2048];
__device__ float g_bhhp[2048];
__device__ float g_Wihp[1024*5];
// duplicated-transposed weights: dup[k][2n] = dup[k][2n+1] = W[n][k]
__device__ float g_WgT [(size_t)256*4096];   // gates: 2048 n
__device__ float g_WlT [(size_t)256*1280];   // logits: 640 n-space (0..399 WbWs, 512..611 Wb)
__device__ float g_W1T [(size_t)KST*1024];   // MLP L1: 512 n
__device__ float g_W2T [(size_t)512*1024];   // MLP L2: 512 n
__device__ float g_W3T [(size_t)512*512];    // MLP L3: 256 n

// ---------------- packed f32x2 helpers ----------------
__device__ __forceinline__ ull ffma2(ull a, ull b, ull c) {
    ull d; asm("fma.rn.f32x2 %0, %1, %2, %3;" : "=l"(d) : "l"(a), "l"(b), "l"(c)); return d;
}
__device__ __forceinline__ void unpack2(ull v, float& lo, float& hi) {
    asm("mov.b64 {%0, %1}, %2;" : "=f"(lo), "=f"(hi) : "l"(v));
}

// ---------------- XLA-GPU-faithful transcendentals ----------------
__device__ __forceinline__ float xla_tanh(float x) {
    float ax = fabsf(x);
    float xc = fminf(fmaxf(x, -7.90531110763549805f), 7.90531110763549805f);
    float x2 = __fmul_rn(xc, xc);
    float p = -2.76076847742355e-16f;
    p = __fadd_rn(__fmul_rn(x2, p),  2.00018790482477e-13f);
    p = __fadd_rn(__fmul_rn(x2, p), -8.60467152213735e-11f);
    p = __fadd_rn(__fmul_rn(x2, p),  5.12229709037114e-08f);
    p = __fadd_rn(__fmul_rn(x2, p),  1.48572235717979e-05f);
    p = __fadd_rn(__fmul_rn(x2, p),  6.37261928875436e-04f);
    p = __fadd_rn(__fmul_rn(x2, p),  4.89352455891786e-03f);
    float num = __fmul_rn(xc, p);
    float q = 1.19825839466702e-06f;
    q = __fadd_rn(__fmul_rn(x2, q), 1.18534705686654e-04f);
    q = __fadd_rn(__fmul_rn(x2, q), 2.26843463243900e-03f);
    q = __fadd_rn(__fmul_rn(x2, q), 4.89352518554385e-03f);
    float r = __fdiv_rn(num, q);
    r = (ax < 0.0004f) ? x : r;
    r = (ax < 20.0f) ? r : copysignf(1.0f, x);
    return r;
}
__device__ __forceinline__ float xla_sigm(float x) {
    return __fdiv_rn(1.0f, __fadd_rn(1.0f, expf(-x)));
}

// ---------------- prep: state copy to output + transposed MLP input -------------
__global__ void prep_kernel(const float* __restrict__ to_t, const float* __restrict__ ti_t,
                            const float* __restrict__ ys_t, float* __restrict__ out_state)
{
    int idx = blockIdx.x * blockDim.x + threadIdx.x;
    if (idx >= BATCH * KST) return;
    int b = idx / KST, i = idx - b * KST;
    const float* src;
    if (i < NBLOCK)            src = to_t + ((size_t)b * NBLOCK + i) * 5;
    else if (i < 2 * NBLOCK)   src = ti_t + ((size_t)b * NBLOCK + (i - NBLOCK)) * 5;
    else                       src = ys_t + ((size_t)b * NYS + (i - 2 * NBLOCK)) * 5;
#pragma unroll
    for (int r = 0; r < 5; r++) {
        float v = src[r];
        out_state[(size_t)idx * 5 + r] = v;
        g_xT[(size_t)(b * 5 + r) * KST + i] = v;
    }
}

// ---------------- weight prep: permuted gate weights + fused logits weight ------
__global__ void prep_weights(const float* __restrict__ Whh_to, const float* __restrict__ Whh_ti,
                             const float* __restrict__ bih_to, const float* __restrict__ bhh_to,
                             const float* __restrict__ bih_ti, const float* __restrict__ bhh_ti,
                             const float* __restrict__ Wih_to,
                             const float* __restrict__ Wb, const float* __restrict__ bb,
                             const float* __restrict__ Ws, const float* __restrict__ bs)
{
    int r = blockIdx.x, j = threadIdx.x;
    int rr = r & 1023, g = rr & 3, jj = rr >> 2;
    int src = g * 256 + jj;
    g_Wg[r * 256 + j] = (r < 1024) ? Whh_to[src * 256 + j] : Whh_ti[src * 256 + j];
    if (j == 0) {
        g_bihp[r] = (r < 1024) ? bih_to[src] : bih_ti[src];
        g_bhhp[r] = (r < 1024) ? bhh_to[src] : bhh_ti[src];
    }
    if (r < 1024 && j < 5) g_Wihp[r * 5 + j] = Wih_to[src * 5 + j];
    if (r < NFUSE) {
        g_WbWs[r * 256 + j] = (r < NBLOCK) ? Wb[r * 256 + j] : Ws[(r - NBLOCK) * 256 + j];
        if (j == 0) g_bf[r] = (r < NBLOCK) ? bb[r] : bs[r - NBLOCK];
    }
}

// dup-transpose: dst[k][2*(n_off+n)] = dst[..+1] = src[n][k]
__global__ void dupT_kernel(float* __restrict__ dst, int ldbd,
                            const float* __restrict__ src, int srcK, int n_off)
{
    int n = blockIdx.x;
    for (int k = threadIdx.x; k < srcK; k += blockDim.x) {
        float v = src[(size_t)n * srcK + k];
        *(float2*)(dst + (size_t)k * ldbd + 2 * (n_off + n)) = make_float2(v, v);
    }
}
__global__ void zfill_kernel(float* __restrict__ dst, int n)
{
    int i = blockIdx.x * 256 + threadIdx.x;
    if (i < n) dst[i] = 0.f;
}

// ---------------- dup-B FFMA2 GEMM core -----------------------------------------
// C[128,128] tile of A[M,K] @ B[N,K]^T using pre-dup-transposed B (BdT[k][2n]).
// Inner loop: 2 A-LDS.128 (m-pairs) + 4 B-LDS.128 (n-splats) + 32 FFMA2, no MOVs.
// Per-output accumulation: k ascending, single accumulator, rn -> bitwise == R4.
#define SASTRIDE 2112   // 16*132 floats per A buffer
#define SBSTRIDE 4096   // 16*256 floats per B buffer
#define SMEM_GEMM  ((2*SASTRIDE + 2*SBSTRIDE) * 4)           // 49664 B
#define SMEM_GATES ((2*SASTRIDE + 2*SBSTRIDE + 1024) * 4)    // 53760 B

__device__ __forceinline__ void gemm_core_d(
    const float* __restrict__ A, int lda,
    const float* __restrict__ BdT, int ldbd,
    int m0, int n0d, int K,
    float* sA, float* sBd, ull acc[4][8])
{
    const int tid = threadIdx.x;
    const int tx = tid & 15, ty = tid >> 4;
#pragma unroll
    for (int i = 0; i < 4; i++)
#pragma unroll
        for (int p = 0; p < 8; p++) acc[i][p] = 0ULL;

    const int T = (K + 15) >> 4;
    // A staging coords (R4-exact)
    const int idx0 = 2 * tid, idx1 = 2 * tid + 1;
    const int ma = idx0 >> 2, kqa = idx0 & 3;
    const int mb = idx1 >> 2, kqb = idx1 & 3;
    const float4 z4 = make_float4(0.f, 0.f, 0.f, 0.f);
    float4 ar0, ar1, br0, br1, br2, br3;
    // B staging coords: 4 chunks of float4; pos = tid + c*256; row=pos>>6, col4=pos&63
    const int brow0 = tid >> 6,        bcol0 = tid & 63;
    const int brow1 = (tid + 256) >> 6,  bcol1 = tid & 63;
    const int brow2 = (tid + 512) >> 6,  bcol2 = tid & 63;
    const int brow3 = (tid + 768) >> 6,  bcol3 = tid & 63;

    // ---- load tile 0 ----
    {
        int gk0 = kqa * 4, gk1 = kqb * 4;
        ar0 = (gk0 < K) ? *(const float4*)(A + (size_t)(m0 + ma) * lda + gk0) : z4;
        ar1 = (gk1 < K) ? *(const float4*)(A + (size_t)(m0 + mb) * lda + gk1) : z4;
        br0 = (brow0 < K) ? *(const float4*)(BdT + (size_t)brow0 * ldbd + n0d + bcol0 * 4) : z4;
        br1 = (brow1 < K) ? *(const float4*)(BdT + (size_t)brow1 * ldbd + n0d + bcol1 * 4) : z4;
        br2 = (brow2 < K) ? *(const float4*)(BdT + (size_t)brow2 * ldbd + n0d + bcol2 * 4) : z4;
        br3 = (brow3 < K) ? *(const float4*)(BdT + (size_t)brow3 * ldbd + n0d + bcol3 * 4) : z4;
        sA[(kqa*4+0)*132+ma]=ar0.x; sA[(kqa*4+1)*132+ma]=ar0.y; sA[(kqa*4+2)*132+ma]=ar0.z; sA[(kqa*4+3)*132+ma]=ar0.w;
        sA[(kqb*4+0)*132+mb]=ar1.x; sA[(kqb*4+1)*132+mb]=ar1.y; sA[(kqb*4+2)*132+mb]=ar1.z; sA[(kqb*4+3)*132+mb]=ar1.w;
        *(float4*)(sBd + brow0 * 256 + bcol0 * 4) = br0;
        *(float4*)(sBd + brow1 * 256 + bcol1 * 4) = br1;
        *(float4*)(sBd + brow2 * 256 + bcol2 * 4) = br2;
        *(float4*)(sBd + brow3 * 256 + bcol3 * 4) = br3;
    }

    for (int t = 0; t < T; t++) {
        __syncthreads();
        if (t + 1 < T) {
            int k0 = (t + 1) << 4;
            int gk0 = k0 + kqa * 4, gk1 = k0 + kqb * 4;
            ar0 = (gk0 < K) ? *(const float4*)(A + (size_t)(m0 + ma) * lda + gk0) : z4;
            ar1 = (gk1 < K) ? *(const float4*)(A + (size_t)(m0 + mb) * lda + gk1) : z4;
            br0 = (k0 + brow0 < K) ? *(const float4*)(BdT + (size_t)(k0 + brow0) * ldbd + n0d + bcol0 * 4) : z4;
            br1 = (k0 + brow1 < K) ? *(const float4*)(BdT + (size_t)(k0 + brow1) * ldbd + n0d + bcol1 * 4) : z4;
            br2 = (k0 + brow2 < K) ? *(const float4*)(BdT + (size_t)(k0 + brow2) * ldbd + n0d + bcol2 * 4) : z4;
            br3 = (k0 + brow3 < K) ? *(const float4*)(BdT + (size_t)(k0 + brow3) * ldbd + n0d + bcol3 * 4) : z4;
        }
        const float* pA  = sA  + (t & 1) * SASTRIDE;
        const float* pBd = sBd + (t & 1) * SBSTRIDE;
#pragma unroll
        for (int kk = 0; kk < 16; kk++) {
            const float* rA = pA + kk * 132;
            float4 av0 = *(const float4*)(rA + ty * 4);        // m pairs 0,1
            float4 av1 = *(const float4*)(rA + 64 + ty * 4);   // m pairs 2,3
            const float* rB = pBd + kk * 256;
            float4 bv0 = *(const float4*)(rB + 8 * tx);        // n splats q0,q1
            float4 bv1 = *(const float4*)(rB + 8 * tx + 4);    // q2,q3
            float4 bv2 = *(const float4*)(rB + 128 + 8 * tx);  // q4,q5
            float4 bv3 = *(const float4*)(rB + 128 + 8 * tx + 4); // q6,q7
            ull ap[4], bs[8];
            ap[0] = ((const ull*)&av0)[0]; ap[1] = ((const ull*)&av0)[1];
            ap[2] = ((const ull*)&av1)[0]; ap[3] = ((const ull*)&av1)[1];
            bs[0] = ((const ull*)&bv0)[0]; bs[1] = ((const ull*)&bv0)[1];
            bs[2] = ((const ull*)&bv1)[0]; bs[3] = ((const ull*)&bv1)[1];
            bs[4] = ((const ull*)&bv2)[0]; bs[5] = ((const ull*)&bv2)[1];
            bs[6] = ((const ull*)&bv3)[0]; bs[7] = ((const ull*)&bv3)[1];
#pragma unroll
            for (int mp = 0; mp < 4; mp++)
#pragma unroll
                for (int q = 0; q < 8; q++)
                    acc[mp][q] = ffma2(ap[mp], bs[q], acc[mp][q]);
        }
        if (t + 1 < T) {
            float* qA  = sA  + ((t + 1) & 1) * SASTRIDE;
            float* qBd = sBd + ((t + 1) & 1) * SBSTRIDE;
            qA[(kqa*4+0)*132+ma]=ar0.x; qA[(kqa*4+1)*132+ma]=ar0.y; qA[(kqa*4+2)*132+ma]=ar0.z; qA[(kqa*4+3)*132+ma]=ar0.w;
            qA[(kqb*4+0)*132+mb]=ar1.x; qA[(kqb*4+1)*132+mb]=ar1.y; qA[(kqb*4+2)*132+mb]=ar1.z; qA[(kqb*4+3)*132+mb]=ar1.w;
            *(float4*)(qBd + brow0 * 256 + bcol0 * 4) = br0;
            *(float4*)(qBd + brow1 * 256 + bcol1 * 4) = br1;
            *(float4*)(qBd + brow2 * 256 + bcol2 * 4) = br2;
            *(float4*)(qBd + brow3 * 256 + bcol3 * 4) = br3;
        }
    }
}

// ---------------- generic GEMM kernel (MLP): +bias, relu ------------------------
__global__ void __launch_bounds__(256, 2) sgemm_d(
    const float* __restrict__ A, int lda,
    const float* __restrict__ BdT, int ldbd,
    const float* __restrict__ bias,
    float* __restrict__ C, int ldc,
    int Nlim, int K, int relu)
{
    extern __shared__ __align__(16) float dyn[];
    float* sA  = dyn;
    float* sBd = dyn + 2 * SASTRIDE;
    ull acc[4][8];
    const int m0 = blockIdx.x * 128, n0 = blockIdx.y * 128;
    gemm_core_d(A, lda, BdT, ldbd, m0, 2 * n0, K, sA, sBd, acc);
    const int tx = threadIdx.x & 15, ty = threadIdx.x >> 4;
#pragma unroll
    for (int mp = 0; mp < 4; mp++) {
#pragma unroll
        for (int half = 0; half < 2; half++) {
            int m = m0 + ((mp >> 1) ? 64 : 0) + ty * 4 + (mp & 1) * 2 + half;
#pragma unroll
            for (int q = 0; q < 8; q++) {
                int nl = (q < 4) ? (tx * 4 + q) : (64 + tx * 4 + (q - 4));
                int n = n0 + nl;
                float lo, hi; unpack2(acc[mp][q], lo, hi);
                float v = half ? hi : lo;
                if (n < Nlim) {
                    v = __fadd_rn(v, bias[n]);
                    if (relu) v = fmaxf(v, 0.f);
                    C[(size_t)m * ldc + n] = v;
                }
            }
        }
    }
}

// ---------------- LSTM cell helpers (R13-exact) ----------------------------------
__device__ __forceinline__ float dot5_fma(const float* s, const float* w) {
    float a = 0.f;
    a = __fmaf_rn(s[0], w[0], a);
    a = __fmaf_rn(s[1], w[1], a);
    a = __fmaf_rn(s[2], w[2], a);
    a = __fmaf_rn(s[3], w[3], a);
    a = __fmaf_rn(s[4], w[4], a);
    return a;
}

__device__ __forceinline__ void cell_apply(int is_ti, const float gv[4], const float* s5,
                                           const float w[4][5], const float* bi, const float* bh,
                                           float* cptr, float* hptr)
{
    float gt[4];
#pragma unroll
    for (int g = 0; g < 4; g++) {
        float d5 = is_ti ? 0.f : dot5_fma(s5, w[g]);
        gt[g] = __fadd_rn(__fadd_rn(__fadd_rn(d5, bi[g]), gv[g]), bh[g]);
    }
    float cold = *cptr;
    float m1 = __fmul_rn(xla_sigm(gt[1]), cold);
    float m2 = __fmul_rn(xla_sigm(gt[0]), xla_tanh(gt[2]));
    float c  = __fadd_rn(m1, m2);
    *cptr = c;
    *hptr = __fmul_rn(xla_sigm(gt[3]), xla_tanh(c));
}

// ---------------- fused gates GEMM + LSTM cell (both tensors per CTA) -----------
__global__ void __launch_bounds__(256, 2) gates_kernel(
    const float* __restrict__ h_to_cur, const float* __restrict__ h_ti_cur,
    float* __restrict__ h_to_nxt, float* __restrict__ h_ti_nxt)
{
    extern __shared__ __align__(16) float dyn[];
    float* sA   = dyn;
    float* sBd  = dyn + 2 * SASTRIDE;
    float* sInp = dyn + 2 * SASTRIDE + 2 * SBSTRIDE;
    ull acc[4][8];
    const int y = blockIdx.y;                    // 0..7
    const int m0 = blockIdx.x * 128;
    const int tid = threadIdx.x;
    const int tx = tid & 15, ty = tid >> 4;

#pragma unroll 1
    for (int tensor = 0; tensor < 2; tensor++) {
        __syncthreads();
        const float* A = tensor ? h_ti_cur : h_to_cur;
        const int n0 = tensor * 1024 + y * 128;  // permuted weight-row offset
        gemm_core_d(A, HIDDIM, g_WgT, 4096, m0, 2 * n0, HIDDIM, sA, sBd, acc);
        __syncthreads();
        if (!tensor) {
            for (int idx = tid; idx < 1024; idx += 256) sInp[idx] = g_inp[m0 * 8 + idx];
            __syncthreads();
        }

        const int jA = y * 32 + tx;              // cell for q=0..3
        const int jB = jA + 16;                  // cell for q=4..7
        const int nA = n0 + tx * 4;
        const int nB = n0 + 64 + tx * 4;

        float biA[4], bhA[4], biB[4], bhB[4];
#pragma unroll
        for (int g = 0; g < 4; g++) {
            biA[g] = g_bihp[nA + g]; bhA[g] = g_bhhp[nA + g];
            biB[g] = g_bihp[nB + g]; bhB[g] = g_bhhp[nB + g];
        }
        float wA[4][5], wB[4][5];
        if (!tensor) {
#pragma unroll
            for (int g = 0; g < 4; g++)
#pragma unroll
                for (int r = 0; r < 5; r++) {
                    wA[g][r] = g_Wihp[(nA + g) * 5 + r];
                    wB[g][r] = g_Wihp[(nB + g) * 5 + r];
                }
        }
        float* cbuf = tensor ? g_c_ti : g_c_to;
        float* hn   = tensor ? h_ti_nxt : h_to_nxt;

#pragma unroll
        for (int mp = 0; mp < 4; mp++) {
            float gaL[4], gaH[4], gbL[4], gbH[4];
#pragma unroll
            for (int q = 0; q < 4; q++) {
                unpack2(acc[mp][q],     gaL[q], gaH[q]);
                unpack2(acc[mp][4 + q], gbL[q], gbH[q]);
            }
            int mlocE = ((mp >> 1) ? 64 : 0) + ty * 4 + (mp & 1) * 2;
#pragma unroll
            for (int half = 0; half < 2; half++) {
                int mloc = mlocE + half;
                int m = m0 + mloc;
                float s5[5];
                if (!tensor) {
#pragma unroll
                    for (int r = 0; r < 5; r++) s5[r] = sInp[mloc * 8 + r];
                }
                const float* ga = half ? gaH : gaL;
                const float* gb = half ? gbH : gbL;
                cell_apply(tensor, ga, s5, wA, biA, bhA, cbuf + (size_t)m * HIDDIM + jA, hn + (size_t)m * HIDDIM + jA);
                cell_apply(tensor, gb, s5, wB, biB, bhB, cbuf + (size_t)m * HIDDIM + jB, hn + (size_t)m * HIDDIM + jB);
            }
        }
    }
}

// ---------------- fused logits GEMM (lto 4 tiles + lti 1 tile) ------------------
__global__ void __launch_bounds__(256, 2) logits_kernel(
    const float* __restrict__ h_to_nxt, const float* __restrict__ h_ti_nxt,
    const float* __restrict__ bb)
{
    extern __shared__ __align__(16) float dyn[];
    float* sA  = dyn;
    float* sBd = dyn + 2 * SASTRIDE;
    ull acc[4][8];
    const int y = blockIdx.y;
    const float* A; const float* bias; float* C; int Nlim, ldc, n0dup, n0out;
    if (y < 4) { A = h_to_nxt; bias = g_bf; C = g_lto; Nlim = NFUSE; ldc = NFUSE; n0dup = y * 128; n0out = y * 128; }
    else       { A = h_ti_nxt; bias = bb;   C = g_lti; Nlim = NBLOCK; ldc = NBLOCK; n0dup = 512; n0out = 0; }
    const int m0 = blockIdx.x * 128;
    gemm_core_d(A, HIDDIM, g_WlT, 1280, m0, 2 * n0dup, HIDDIM, sA, sBd, acc);
    const int tx = threadIdx.x & 15, ty = threadIdx.x >> 4;
#pragma unroll
    for (int mp = 0; mp < 4; mp++) {
#pragma unroll
        for (int half = 0; half < 2; half++) {
            int m = m0 + ((mp >> 1) ? 64 : 0) + ty * 4 + (mp & 1) * 2 + half;
#pragma unroll
            for (int q = 0; q < 8; q++) {
                int nl = (q < 4) ? (tx * 4 + q) : (64 + tx * 4 + (q - 4));
                int n = n0out + nl;
                float lo, hi; unpack2(acc[mp][q], lo, hi);
                float v = half ? hi : lo;
                if (n < Nlim) C[(size_t)m * ldc + n] = __fadd_rn(v, bias[n]);
            }
        }
    }
}

// ---------------- feat_vec + carry init ----------------
__global__ void feat_init_kernel(const float* __restrict__ W_fe2, const float* __restrict__ b_fe2,
                                 const float* __restrict__ to_t, const float* __restrict__ ti_t,
                                 const float* __restrict__ slot_info)
{
    int b = blockIdx.x, j = threadIdx.x;
    float f = 0.f;
#pragma unroll
    for (int r = 0; r < 5; r++)
        f = __fmaf_rn(g_act3[(size_t)(b * 5 + r) * HIDDIM + j], W_fe2[r], f);
    f = __fadd_rn(f, b_fe2[0]);
    g_h_to[0][b * HIDDIM + j] = f;
    g_h_ti[0][b * HIDDIM + j] = f;
    g_c_to[b * HIDDIM + j] = 0.f;
    g_c_ti[b * HIDDIM + j] = 0.f;
    if (j < 8) g_inp[b * 8 + j] = 0.f;
    if (j < NBLOCK) {
        g_mto[b * NBLOCK + j] = (to_t[((size_t)b * NBLOCK + j) * 5] != -1.0f);
        g_mti[b * NBLOCK + j] = (ti_t[((size_t)b * NBLOCK + j) * 5] != -1.0f);
    }
    for (int i = j; i < NSLOT; i += HIDDIM) {
        const float* sl = slot_info + ((size_t)b * NSLOT + i) * 5;
        g_sl0 [(size_t)b * NSLOT + i] = sl[0];
        g_sw0 [(size_t)b * NSLOT + i] = sl[1];
        g_scnt[(size_t)b * NSLOT + i] = sl[4];
    }
}

// ---------------- warp-per-batch masked argmax + state mutation -----------------
__global__ void select_kernel(const float* __restrict__ to_t, float* __restrict__ out_act, int step)
{
    const int w = threadIdx.x >> 5, l = threadIdx.x & 31;
    const int b = blockIdx.x * 4 + w;

    float v = -3.4e38f; int bi = 0x7fffffff;
    for (int i = l; i < NBLOCK; i += 32) {
        float lv = g_mto[b * NBLOCK + i] ? g_lto[(size_t)b * NFUSE + i] : NEGV;
        if (lv > v || (lv == v && i < bi)) { v = lv; bi = i; }
    }
#pragma unroll
    for (int o = 16; o; o >>= 1) {
        float v2 = __shfl_xor_sync(0xffffffffu, v, o);
        int   i2 = __shfl_xor_sync(0xffffffffu, bi, o);
        if (v2 > v || (v2 == v && i2 < bi)) { v = v2; bi = i2; }
    }
    const int sel_b = bi;
    if (l == 0) {
        g_mto[b * NBLOCK + sel_b] = 0;
#pragma unroll
        for (int r = 0; r < 5; r++)
            g_inp[b * 8 + r] = to_t[((size_t)b * NBLOCK + sel_b) * 5 + r];
    }
    const float bl0 = to_t[((size_t)b * NBLOCK + sel_b) * 5 + 0];
    const float bl1 = to_t[((size_t)b * NBLOCK + sel_b) * 5 + 1];

    v = -3.4e38f; bi = 0x7fffffff;
    for (int i = l; i < NSLOT; i += 32) {
        float l0 = g_sl0[(size_t)b * NSLOT + i];
        float w0 = g_sw0[(size_t)b * NSLOT + i];
        bool bad = (bl0 >= l0) || (bl1 >= w0) || (l0 == 0.0f);
        float lv = bad ? NEGV : g_lto[(size_t)b * NFUSE + NBLOCK + i];
        if (lv > v || (lv == v && i < bi)) { v = lv; bi = i; }
    }
#pragma unroll
    for (int o = 16; o; o >>= 1) {
        float v2 = __shfl_xor_sync(0xffffffffu, v, o);
        int   i2 = __shfl_xor_sync(0xffffffffu, bi, o);
        if (v2 > v || (v2 == v && i2 < bi)) { v = v2; bi = i2; }
    }
    const int sel_s = bi;
    if (l == 0) {
        size_t si = (size_t)b * NSLOT + sel_s;
        float cnt = __fadd_rn(g_scnt[si], -1.0f);
        g_scnt[si] = cnt;
        if (cnt == 0.0f) { g_sl0[si] = 0.f; g_sw0[si] = 0.f; }
    }

    v = -3.4e38f; bi = 0x7fffffff;
    for (int i = l; i < NBLOCK; i += 32) {
        float lv = g_mti[b * NBLOCK + i] ? g_lti[(size_t)b * NBLOCK + i] : NEGV;
        if (lv > v || (lv == v && i < bi)) { v = lv; bi = i; }
    }
#pragma unroll
    for (int o = 16; o; o >>= 1) {
        float v2 = __shfl_xor_sync(0xffffffffu, v, o);
        int   i2 = __shfl_xor_sync(0xffffffffu, bi, o);
        if (v2 > v || (v2 == v && i2 < bi)) { v = v2; bi = i2; }
    }
    if (l == 0) {
        g_mti[b * NBLOCK + bi] = 0;
        float* oa = out_act + ((size_t)b * NSTEPS + step) * 3;
        oa[0] = (float)sel_b;
        oa[1] = (float)sel_s;
        oa[2] = (float)bi;
    }
}

// ---------------- launch ----------------
extern "C" void kernel_launch(void* const* d_in, const int* in_sizes, int n_in,
                              void* d_out, int out_size)
{
    const float* to_t    = (const float*)d_in[0];
    const float* ti_t    = (const float*)d_in[1];
    const float* ys_t    = (const float*)d_in[2];
    const float* slot    = (const float*)d_in[3];
    const float* W1      = (const float*)d_in[4];
    const float* b1      = (const float*)d_in[5];
    const float* W2      = (const float*)d_in[6];
    const float* b2      = (const float*)d_in[7];
    const float* W3      = (const float*)d_in[8];
    const float* b3      = (const float*)d_in[9];
    const float* W_fe2   = (const float*)d_in[10];
    const float* b_fe2   = (const float*)d_in[11];
    const float* Wih_to  = (const float*)d_in[12];
    const float* Whh_to  = (const float*)d_in[13];
    const float* bih_to  = (const float*)d_in[14];
    const float* bhh_to  = (const float*)d_in[15];
    const float* Whh_ti  = (const float*)d_in[17];
    const float* bih_ti  = (const float*)d_in[18];
    const float* bhh_ti  = (const float*)d_in[19];
    const float* Wb      = (const float*)d_in[20];
    const float* bb      = (const float*)d_in[21];
    const float* Ws      = (const float*)d_in[22];
    const float* bs      = (const float*)d_in[23];

    float* out     = (float*)d_out;
    float* out_act = out + (size_t)BATCH * KST * 5;

    float *p_xT, *p_a1, *p_a2, *p_a3, *p_hto, *p_hti;
    float *p_Wg, *p_WbWs, *p_WgT, *p_WlT, *p_W1T, *p_W2T, *p_W3T;
    cudaGetSymbolAddress((void**)&p_xT,   g_xT);
    cudaGetSymbolAddress((void**)&p_a1,   g_act1);
    cudaGetSymbolAddress((void**)&p_a2,   g_act2);
    cudaGetSymbolAddress((void**)&p_a3,   g_act3);
    cudaGetSymbolAddress((void**)&p_hto,  g_h_to);
    cudaGetSymbolAddress((void**)&p_hti,  g_h_ti);
    cudaGetSymbolAddress((void**)&p_Wg,   g_Wg);
    cudaGetSymbolAddress((void**)&p_WbWs, g_WbWs);
    cudaGetSymbolAddress((void**)&p_WgT,  g_WgT);
    cudaGetSymbolAddress((void**)&p_WlT,  g_WlT);
    cudaGetSymbolAddress((void**)&p_W1T,  g_W1T);
    cudaGetSymbolAddress((void**)&p_W2T,  g_W2T);
    cudaGetSymbolAddress((void**)&p_W3T,  g_W3T);
    float* h_to_buf[2] = { p_hto, p_hto + BATCH * HIDDIM };
    float* h_ti_buf[2] = { p_hti, p_hti + BATCH * HIDDIM };

    static int attr_done = 0;
    if (!attr_done) {
        cudaFuncSetAttribute(sgemm_d,       cudaFuncAttributeMaxDynamicSharedMemorySize, SMEM_GEMM);
        cudaFuncSetAttribute(logits_kernel, cudaFuncAttributeMaxDynamicSharedMemorySize, SMEM_GEMM);
        cudaFuncSetAttribute(gates_kernel,  cudaFuncAttributeMaxDynamicSharedMemorySize, SMEM_GATES);
        attr_done = 1;
    }

    // prep
    int nprep = (BATCH * KST + 255) / 256;
    prep_kernel<<<nprep, 256>>>(to_t, ti_t, ys_t, out);
    prep_weights<<<2048, 256>>>(Whh_to, Whh_ti, bih_to, bhh_to, bih_ti, bhh_ti,
                                Wih_to, Wb, bb, Ws, bs);
    // dup-transposed weights
    zfill_kernel<<<(256 * 1280 + 255) / 256, 256>>>(p_WlT, 256 * 1280);
    dupT_kernel<<<2048, 256>>>(p_WgT, 4096, p_Wg, 256, 0);
    dupT_kernel<<<400, 256>>>(p_WlT, 1280, p_WbWs, 256, 0);
    dupT_kernel<<<100, 256>>>(p_WlT, 1280, Wb, 256, 512);
    dupT_kernel<<<512, 256>>>(p_W1T, 1024, W1, KST, 0);
    dupT_kernel<<<512, 256>>>(p_W2T, 1024, W2, 512, 0);
    dupT_kernel<<<256, 256>>>(p_W3T, 512, W3, 512, 0);

    // MLP
    dim3 g1(M5 / 128, 4);
    sgemm_d<<<g1, 256, SMEM_GEMM>>>(p_xT, KST, p_W1T, 1024, b1, p_a1, 512, 512, KST, 1);
    sgemm_d<<<g1, 256, SMEM_GEMM>>>(p_a1, 512, p_W2T, 1024, b2, p_a2, 512, 512, 512, 1);
    dim3 g3(M5 / 128, 2);
    sgemm_d<<<g3, 256, SMEM_GEMM>>>(p_a2, 512, p_W3T, 512, b3, p_a3, 256, 256, 512, 1);
    feat_init_kernel<<<BATCH, HIDDIM>>>(W_fe2, b_fe2, to_t, ti_t, slot);

    dim3 gg(BATCH / 128, 8);
    dim3 gl(BATCH / 128, 5);
    for (int s = 0; s < NSTEPS; s++) {
        int cur = s & 1, nxt = cur ^ 1;
        gates_kernel <<<gg, 256, SMEM_GATES>>>(h_to_buf[cur], h_ti_buf[cur], h_to_buf[nxt], h_ti_buf[nxt]);
        logits_kernel<<<gl, 256, SMEM_GEMM>>>(h_to_buf[nxt], h_ti_buf[nxt], bb);
        select_kernel<<<BATCH / 4, 128>>>(to_t, out_act, s);
    }
}

// round 17
// speedup vs baseline: 1.4470x; 1.4470x over previous
#include <cuda_runtime.h>
#include <math.h>
#include <stdint.h>

// ---------------- problem constants ----------------
#define BATCH   4096
#define NBLOCK  100
#define NSLOT   300
#define NYS     1236
#define HIDDIM  256
#define NSTEPS  100
#define KST     1436        // 100 + 100 + 1236
#define M5      (BATCH*5)
#define NFUSE   (NBLOCK+NSLOT) // 400
#define NEGV    (-1000.0f)

typedef unsigned long long ull;

// ---------------- scratch (device globals; no allocs allowed) ----------------
__device__ float g_xT  [(size_t)M5 * KST];
__device__ float g_act1[(size_t)M5 * 512];
__device__ float g_act2[(size_t)M5 * 512];
__device__ float g_act3[(size_t)M5 * 256];
__device__ float g_h_to[2][BATCH*HIDDIM];
__device__ float g_c_to[BATCH*HIDDIM];
__device__ float g_h_ti[2][BATCH*HIDDIM];
__device__ float g_c_ti[BATCH*HIDDIM];
__device__ float g_lto [(size_t)BATCH*NFUSE];
__device__ float g_lti [(size_t)BATCH*NBLOCK];
__device__ float g_inp [BATCH*8];
__device__ unsigned char g_mto[BATCH*NBLOCK];
__device__ unsigned char g_mti[BATCH*NBLOCK];
// SoA slot state
__device__ float g_sl0 [(size_t)BATCH*NSLOT];
__device__ float g_sw0 [(size_t)BATCH*NSLOT];
__device__ float g_scnt[(size_t)BATCH*NSLOT];
__device__ float g_WbWs[NFUSE*HIDDIM];
__device__ float g_bf  [NFUSE];
// permuted gate weights: row 4j+g (to: rows 0..1023, ti: rows 1024..2047)
__device__ float g_Wg  [2048*HIDDIM];
__device__ float g_bihp[2048];
__device__ float g_bhhp[2048];
__device__ float g_Wihp[1024*5];
// dup-transposed weights, per-128n-tile permuted splat layout (see dupT_kernel)
__device__ float g_WgT [(size_t)256*4096];   // gates: 16 tiles
__device__ float g_WlT [(size_t)256*1280];   // logits: 5 tiles (0..3 WbWs, 4 Wb)
__device__ float g_W1T [(size_t)KST*1024];   // MLP L1: 4 tiles
__device__ float g_W2T [(size_t)512*1024];   // MLP L2: 4 tiles
__device__ float g_W3T [(size_t)512*512];    // MLP L3: 2 tiles

// ---------------- packed f32x2 helpers ----------------
__device__ __forceinline__ ull ffma2(ull a, ull b, ull c) {
    ull d; asm("fma.rn.f32x2 %0, %1, %2, %3;" : "=l"(d) : "l"(a), "l"(b), "l"(c)); return d;
}
__device__ __forceinline__ void unpack2(ull v, float& lo, float& hi) {
    asm("mov.b64 {%0, %1}, %2;" : "=f"(lo), "=f"(hi) : "l"(v));
}
__device__ __forceinline__ uint32_t smem_u32(const void* p) {
    uint32_t a; asm("{ .reg .u64 t; cvta.to.shared.u64 t, %1; cvt.u32.u64 %0, t; }" : "=r"(a) : "l"(p));
    return a;
}
__device__ __forceinline__ void cpa16(uint32_t dst, const void* src, int szbytes) {
    asm volatile("cp.async.cg.shared.global [%0], [%1], 16, %2;"
                 :: "r"(dst), "l"(src), "r"(szbytes) : "memory");
}
#define CPA_COMMIT() asm volatile("cp.async.commit_group;" ::: "memory")
#define CPA_WAIT0()  asm volatile("cp.async.wait_group 0;" ::: "memory")

// ---------------- XLA-GPU-faithful transcendentals ----------------
__device__ __forceinline__ float xla_tanh(float x) {
    float ax = fabsf(x);
    float xc = fminf(fmaxf(x, -7.90531110763549805f), 7.90531110763549805f);
    float x2 = __fmul_rn(xc, xc);
    float p = -2.76076847742355e-16f;
    p = __fadd_rn(__fmul_rn(x2, p),  2.00018790482477e-13f);
    p = __fadd_rn(__fmul_rn(x2, p), -8.60467152213735e-11f);
    p = __fadd_rn(__fmul_rn(x2, p),  5.12229709037114e-08f);
    p = __fadd_rn(__fmul_rn(x2, p),  1.48572235717979e-05f);
    p = __fadd_rn(__fmul_rn(x2, p),  6.37261928875436e-04f);
    p = __fadd_rn(__fmul_rn(x2, p),  4.89352455891786e-03f);
    float num = __fmul_rn(xc, p);
    float q = 1.19825839466702e-06f;
    q = __fadd_rn(__fmul_rn(x2, q), 1.18534705686654e-04f);
    q = __fadd_rn(__fmul_rn(x2, q), 2.26843463243900e-03f);
    q = __fadd_rn(__fmul_rn(x2, q), 4.89352518554385e-03f);
    float r = __fdiv_rn(num, q);
    r = (ax < 0.0004f) ? x : r;
    r = (ax < 20.0f) ? r : copysignf(1.0f, x);
    return r;
}
__device__ __forceinline__ float xla_sigm(float x) {
    return __fdiv_rn(1.0f, __fadd_rn(1.0f, expf(-x)));
}

// ---------------- prep: state copy to output + transposed MLP input -------------
__global__ void prep_kernel(const float* __restrict__ to_t, const float* __restrict__ ti_t,
                            const float* __restrict__ ys_t, float* __restrict__ out_state)
{
    int idx = blockIdx.x * blockDim.x + threadIdx.x;
    if (idx >= BATCH * KST) return;
    int b = idx / KST, i = idx - b * KST;
    const float* src;
    if (i < NBLOCK)            src = to_t + ((size_t)b * NBLOCK + i) * 5;
    else if (i < 2 * NBLOCK)   src = ti_t + ((size_t)b * NBLOCK + (i - NBLOCK)) * 5;
    else                       src = ys_t + ((size_t)b * NYS + (i - 2 * NBLOCK)) * 5;
#pragma unroll
    for (int r = 0; r < 5; r++) {
        float v = src[r];
        out_state[(size_t)idx * 5 + r] = v;
        g_xT[(size_t)(b * 5 + r) * KST + i] = v;
    }
}

// ---------------- weight prep: permuted gate weights + fused logits weight ------
__global__ void prep_weights(const float* __restrict__ Whh_to, const float* __restrict__ Whh_ti,
                             const float* __restrict__ bih_to, const float* __restrict__ bhh_to,
                             const float* __restrict__ bih_ti, const float* __restrict__ bhh_ti,
                             const float* __restrict__ Wih_to,
                             const float* __restrict__ Wb, const float* __restrict__ bb,
                             const float* __restrict__ Ws, const float* __restrict__ bs)
{
    int r = blockIdx.x, j = threadIdx.x;
    int rr = r & 1023, g = rr & 3, jj = rr >> 2;
    int src = g * 256 + jj;
    g_Wg[r * 256 + j] = (r < 1024) ? Whh_to[src * 256 + j] : Whh_ti[src * 256 + j];
    if (j == 0) {
        g_bihp[r] = (r < 1024) ? bih_to[src] : bih_ti[src];
        g_bhhp[r] = (r < 1024) ? bhh_to[src] : bhh_ti[src];
    }
    if (r < 1024 && j < 5) g_Wihp[r * 5 + j] = Wih_to[src * 5 + j];
    if (r < NFUSE) {
        g_WbWs[r * 256 + j] = (r < NBLOCK) ? Wb[r * 256 + j] : Ws[(r - NBLOCK) * 256 + j];
        if (j == 0) g_bf[r] = (r < NBLOCK) ? bb[r] : bs[r - NBLOCK];
    }
}

// dup-transpose with per-128n-tile permuted splat layout.
// n-space position p = n_off + blockIdx.x -> tile = p>>7, nl = p&127.
// (tx,q) from nl:  nl<64: tx=nl>>2,q=nl&3  else tx=(nl-64)>>2,q=4+((nl-64)&3)
// word within tile row (256 words): w = (q>>1)*64 + tx*4 + 2*(q&1); {v,v} at w,w+1.
__global__ void dupT_kernel(float* __restrict__ dst, int ldbd,
                            const float* __restrict__ src, int srcK, int n_off)
{
    int n = blockIdx.x;
    int p = n_off + n;
    int tile = p >> 7, nl = p & 127;
    int tx, q;
    if (nl < 64) { tx = nl >> 2; q = nl & 3; }
    else         { tx = (nl - 64) >> 2; q = 4 + ((nl - 64) & 3); }
    int w = (q >> 1) * 64 + tx * 4 + 2 * (q & 1);
    for (int k = threadIdx.x; k < srcK; k += blockDim.x) {
        float v = src[(size_t)n * srcK + k];
        *(float2*)(dst + (size_t)k * ldbd + tile * 256 + w) = make_float2(v, v);
    }
}
__global__ void zfill_kernel(float* __restrict__ dst, int n)
{
    int i = blockIdx.x * 256 + threadIdx.x;
    if (i < n) dst[i] = 0.f;
}

// ---------------- dup-B FFMA2 GEMM core (cp.async B, conflict-free) -------------
// Inner loop: 2 A-LDS.128 + 4 B-LDS.128 + 32 FFMA2, no MOVs, no spills.
// Accumulation per output: k ascending, single accumulator, rn -> bitwise == R4.
#define SASTRIDE 2112   // 16*132 floats per A buffer
#define SBSTRIDE 4096   // 16*256 floats per B buffer
#define SMEM_GEMM  ((2*SASTRIDE + 2*SBSTRIDE) * 4)           // 49664 B
#define SMEM_GATES ((2*SASTRIDE + 2*SBSTRIDE + 1024) * 4)    // 53760 B

__device__ __forceinline__ void gemm_core_d(
    const float* __restrict__ A, int lda,
    const float* __restrict__ BdT, int ldbd,
    int m0, int n0w, int K,                 // n0w = tile word base = (n0>>7)*256
    float* sA, float* sBd, ull acc[4][8])
{
    const int tid = threadIdx.x;
    const int tx = tid & 15, ty = tid >> 4;
#pragma unroll
    for (int i = 0; i < 4; i++)
#pragma unroll
        for (int p = 0; p < 8; p++) acc[i][p] = 0ULL;

    const int T = (K + 15) >> 4;
    // A staging coords (R4-exact)
    const int idx0 = 2 * tid, idx1 = 2 * tid + 1;
    const int ma = idx0 >> 2, kqa = idx0 & 3;
    const int mb = idx1 >> 2, kqb = idx1 & 3;
    const float4 z4 = make_float4(0.f, 0.f, 0.f, 0.f);
    float4 ar0, ar1;
    const uint32_t sBd_b = smem_u32(sBd);
    const int bcol = tid & 63;

    // ---- prologue: tile 0 ----
    {
        int gk0 = kqa * 4, gk1 = kqb * 4;
        ar0 = (gk0 < K) ? *(const float4*)(A + (size_t)(m0 + ma) * lda + gk0) : z4;
        ar1 = (gk1 < K) ? *(const float4*)(A + (size_t)(m0 + mb) * lda + gk1) : z4;
#pragma unroll
        for (int c = 0; c < 4; c++) {
            int row = (tid + 256 * c) >> 6;
            int gk = row;
            const float* src = BdT + (size_t)(gk < K ? gk : 0) * ldbd + n0w + bcol * 4;
            cpa16(sBd_b + (uint32_t)(row * 256 + bcol * 4) * 4, src, (gk < K) ? 16 : 0);
        }
        CPA_COMMIT();
        sA[(kqa*4+0)*132+ma]=ar0.x; sA[(kqa*4+1)*132+ma]=ar0.y; sA[(kqa*4+2)*132+ma]=ar0.z; sA[(kqa*4+3)*132+ma]=ar0.w;
        sA[(kqb*4+0)*132+mb]=ar1.x; sA[(kqb*4+1)*132+mb]=ar1.y; sA[(kqb*4+2)*132+mb]=ar1.z; sA[(kqb*4+3)*132+mb]=ar1.w;
        CPA_WAIT0();
    }

    for (int t = 0; t < T; t++) {
        __syncthreads();
        const int nbuf = (t + 1) & 1;
        if (t + 1 < T) {
            int k0 = (t + 1) << 4;
            int gk0 = k0 + kqa * 4, gk1 = k0 + kqb * 4;
            ar0 = (gk0 < K) ? *(const float4*)(A + (size_t)(m0 + ma) * lda + gk0) : z4;
            ar1 = (gk1 < K) ? *(const float4*)(A + (size_t)(m0 + mb) * lda + gk1) : z4;
#pragma unroll
            for (int c = 0; c < 4; c++) {
                int row = (tid + 256 * c) >> 6;
                int gk = k0 + row;
                const float* src = BdT + (size_t)(gk < K ? gk : 0) * ldbd + n0w + bcol * 4;
                cpa16(sBd_b + (uint32_t)(nbuf * SBSTRIDE + row * 256 + bcol * 4) * 4, src, (gk < K) ? 16 : 0);
            }
            CPA_COMMIT();
        }
        const float* pA  = sA  + (t & 1) * SASTRIDE;
        const float* pBd = sBd + (t & 1) * SBSTRIDE;
#pragma unroll
        for (int kk = 0; kk < 16; kk++) {
            const float* rA = pA + kk * 132;
            float4 av0 = *(const float4*)(rA + ty * 4);           // m pairs 0,1
            float4 av1 = *(const float4*)(rA + 64 + ty * 4);      // m pairs 2,3
            const float* rB = pBd + kk * 256;
            float4 bv0 = *(const float4*)(rB + 4 * tx);           // {q0,q0,q1,q1}
            float4 bv1 = *(const float4*)(rB + 64 + 4 * tx);      // {q2,q2,q3,q3}
            float4 bv2 = *(const float4*)(rB + 128 + 4 * tx);     // {q4,q4,q5,q5}
            float4 bv3 = *(const float4*)(rB + 192 + 4 * tx);     // {q6,q6,q7,q7}
            ull ap[4], bs[8];
            ap[0] = ((const ull*)&av0)[0]; ap[1] = ((const ull*)&av0)[1];
            ap[2] = ((const ull*)&av1)[0]; ap[3] = ((const ull*)&av1)[1];
            bs[0] = ((const ull*)&bv0)[0]; bs[1] = ((const ull*)&bv0)[1];
            bs[2] = ((const ull*)&bv1)[0]; bs[3] = ((const ull*)&bv1)[1];
            bs[4] = ((const ull*)&bv2)[0]; bs[5] = ((const ull*)&bv2)[1];
            bs[6] = ((const ull*)&bv3)[0]; bs[7] = ((const ull*)&bv3)[1];
#pragma unroll
            for (int mp = 0; mp < 4; mp++)
#pragma unroll
                for (int q = 0; q < 8; q++)
                    acc[mp][q] = ffma2(ap[mp], bs[q], acc[mp][q]);
        }
        if (t + 1 < T) {
            float* qA = sA + nbuf * SASTRIDE;
            qA[(kqa*4+0)*132+ma]=ar0.x; qA[(kqa*4+1)*132+ma]=ar0.y; qA[(kqa*4+2)*132+ma]=ar0.z; qA[(kqa*4+3)*132+ma]=ar0.w;
            qA[(kqb*4+0)*132+mb]=ar1.x; qA[(kqb*4+1)*132+mb]=ar1.y; qA[(kqb*4+2)*132+mb]=ar1.z; qA[(kqb*4+3)*132+mb]=ar1.w;
            CPA_WAIT0();
        }
    }
}

// ---------------- generic GEMM kernel (MLP): +bias, relu ------------------------
__global__ void __launch_bounds__(256, 2) sgemm_d(
    const float* __restrict__ A, int lda,
    const float* __restrict__ BdT, int ldbd,
    const float* __restrict__ bias,
    float* __restrict__ C, int ldc,
    int Nlim, int K, int relu)
{
    extern __shared__ __align__(16) float dyn[];
    float* sA  = dyn;
    float* sBd = dyn + 2 * SASTRIDE;
    ull acc[4][8];
    const int m0 = blockIdx.x * 128, n0 = blockIdx.y * 128;
    gemm_core_d(A, lda, BdT, ldbd, m0, blockIdx.y * 256, K, sA, sBd, acc);
    const int tx = threadIdx.x & 15, ty = threadIdx.x >> 4;
#pragma unroll
    for (int mp = 0; mp < 4; mp++) {
#pragma unroll
        for (int half = 0; half < 2; half++) {
            int m = m0 + ((mp >> 1) ? 64 : 0) + ty * 4 + (mp & 1) * 2 + half;
#pragma unroll
            for (int q = 0; q < 8; q++) {
                int nl = (q < 4) ? (tx * 4 + q) : (64 + tx * 4 + (q - 4));
                int n = n0 + nl;
                float lo, hi; unpack2(acc[mp][q], lo, hi);
                float v = half ? hi : lo;
                if (n < Nlim) {
                    v = __fadd_rn(v, bias[n]);
                    if (relu) v = fmaxf(v, 0.f);
                    C[(size_t)m * ldc + n] = v;
                }
            }
        }
    }
}

// ---------------- LSTM cell helpers (R13-exact) ----------------------------------
__device__ __forceinline__ float dot5_fma(const float* s, const float* w) {
    float a = 0.f;
    a = __fmaf_rn(s[0], w[0], a);
    a = __fmaf_rn(s[1], w[1], a);
    a = __fmaf_rn(s[2], w[2], a);
    a = __fmaf_rn(s[3], w[3], a);
    a = __fmaf_rn(s[4], w[4], a);
    return a;
}

__device__ __forceinline__ void cell_apply(int is_ti, const float gv[4], const float* s5,
                                           const float w[4][5], const float* bi, const float* bh,
                                           float* cptr, float* hptr)
{
    float gt[4];
#pragma unroll
    for (int g = 0; g < 4; g++) {
        float d5 = is_ti ? 0.f : dot5_fma(s5, w[g]);
        gt[g] = __fadd_rn(__fadd_rn(__fadd_rn(d5, bi[g]), gv[g]), bh[g]);
    }
    float cold = *cptr;
    float m1 = __fmul_rn(xla_sigm(gt[1]), cold);
    float m2 = __fmul_rn(xla_sigm(gt[0]), xla_tanh(gt[2]));
    float c  = __fadd_rn(m1, m2);
    *cptr = c;
    *hptr = __fmul_rn(xla_sigm(gt[3]), xla_tanh(c));
}

// ---------------- fused gates GEMM + LSTM cell (both tensors per CTA) -----------
__global__ void __launch_bounds__(256, 2) gates_kernel(
    const float* __restrict__ h_to_cur, const float* __restrict__ h_ti_cur,
    float* __restrict__ h_to_nxt, float* __restrict__ h_ti_nxt)
{
    extern __shared__ __align__(16) float dyn[];
    float* sA   = dyn;
    float* sBd  = dyn + 2 * SASTRIDE;
    float* sInp = dyn + 2 * SASTRIDE + 2 * SBSTRIDE;
    ull acc[4][8];
    const int y = blockIdx.y;                    // 0..7
    const int m0 = blockIdx.x * 128;
    const int tid = threadIdx.x;
    const int tx = tid & 15, ty = tid >> 4;

#pragma unroll 1
    for (int tensor = 0; tensor < 2; tensor++) {
        __syncthreads();
        const float* A = tensor ? h_ti_cur : h_to_cur;
        const int n0 = tensor * 1024 + y * 128;  // permuted weight-row offset
        gemm_core_d(A, HIDDIM, g_WgT, 4096, m0, (tensor * 8 + y) * 256, HIDDIM, sA, sBd, acc);
        __syncthreads();
        if (!tensor) {
            for (int idx = tid; idx < 1024; idx += 256) sInp[idx] = g_inp[m0 * 8 + idx];
            __syncthreads();
        }

        const int jA = y * 32 + tx;              // cell for q=0..3
        const int jB = jA + 16;                  // cell for q=4..7
        const int nA = n0 + tx * 4;
        const int nB = n0 + 64 + tx * 4;

        float biA[4], bhA[4], biB[4], bhB[4];
#pragma unroll
        for (int g = 0; g < 4; g++) {
            biA[g] = g_bihp[nA + g]; bhA[g] = g_bhhp[nA + g];
            biB[g] = g_bihp[nB + g]; bhB[g] = g_bhhp[nB + g];
        }
        float wA[4][5], wB[4][5];
        if (!tensor) {
#pragma unroll
            for (int g = 0; g < 4; g++)
#pragma unroll
                for (int r = 0; r < 5; r++) {
                    wA[g][r] = g_Wihp[(nA + g) * 5 + r];
                    wB[g][r] = g_Wihp[(nB + g) * 5 + r];
                }
        }
        float* cbuf = tensor ? g_c_ti : g_c_to;
        float* hn   = tensor ? h_ti_nxt : h_to_nxt;

#pragma unroll
        for (int mp = 0; mp < 4; mp++) {
            float gaL[4], gaH[4], gbL[4], gbH[4];
#pragma unroll
            for (int q = 0; q < 4; q++) {
                unpack2(acc[mp][q],     gaL[q], gaH[q]);
                unpack2(acc[mp][4 + q], gbL[q], gbH[q]);
            }
            int mlocE = ((mp >> 1) ? 64 : 0) + ty * 4 + (mp & 1) * 2;
#pragma unroll
            for (int half = 0; half < 2; half++) {
                int mloc = mlocE + half;
                int m = m0 + mloc;
                float s5[5];
                if (!tensor) {
#pragma unroll
                    for (int r = 0; r < 5; r++) s5[r] = sInp[mloc * 8 + r];
                }
                const float* ga = half ? gaH : gaL;
                const float* gb = half ? gbH : gbL;
                cell_apply(tensor, ga, s5, wA, biA, bhA, cbuf + (size_t)m * HIDDIM + jA, hn + (size_t)m * HIDDIM + jA);
                cell_apply(tensor, gb, s5, wB, biB, bhB, cbuf + (size_t)m * HIDDIM + jB, hn + (size_t)m * HIDDIM + jB);
            }
        }
    }
}

// ---------------- fused logits GEMM (lto 4 tiles + lti 1 tile) ------------------
__global__ void __launch_bounds__(256, 2) logits_kernel(
    const float* __restrict__ h_to_nxt, const float* __restrict__ h_ti_nxt,
    const float* __restrict__ bb)
{
    extern __shared__ __align__(16) float dyn[];
    float* sA  = dyn;
    float* sBd = dyn + 2 * SASTRIDE;
    ull acc[4][8];
    const int y = blockIdx.y;
    const float* A; const float* bias; float* C; int Nlim, ldc, n0out, tile;
    if (y < 4) { A = h_to_nxt; bias = g_bf; C = g_lto; Nlim = NFUSE; ldc = NFUSE; n0out = y * 128; tile = y; }
    else       { A = h_ti_nxt; bias = bb;   C = g_lti; Nlim = NBLOCK; ldc = NBLOCK; n0out = 0; tile = 4; }
    const int m0 = blockIdx.x * 128;
    gemm_core_d(A, HIDDIM, g_WlT, 1280, m0, tile * 256, HIDDIM, sA, sBd, acc);
    const int tx = threadIdx.x & 15, ty = threadIdx.x >> 4;
#pragma unroll
    for (int mp = 0; mp < 4; mp++) {
#pragma unroll
        for (int half = 0; half < 2; half++) {
            int m = m0 + ((mp >> 1) ? 64 : 0) + ty * 4 + (mp & 1) * 2 + half;
#pragma unroll
            for (int q = 0; q < 8; q++) {
                int nl = (q < 4) ? (tx * 4 + q) : (64 + tx * 4 + (q - 4));
                int n = n0out + nl;
                float lo, hi; unpack2(acc[mp][q], lo, hi);
                float v = half ? hi : lo;
                if (n < Nlim) C[(size_t)m * ldc + n] = __fadd_rn(v, bias[n]);
            }
        }
    }
}

// ---------------- feat_vec + carry init ----------------
__global__ void feat_init_kernel(const float* __restrict__ W_fe2, const float* __restrict__ b_fe2,
                                 const float* __restrict__ to_t, const float* __restrict__ ti_t,
                                 const float* __restrict__ slot_info)
{
    int b = blockIdx.x, j = threadIdx.x;
    float f = 0.f;
#pragma unroll
    for (int r = 0; r < 5; r++)
        f = __fmaf_rn(g_act3[(size_t)(b * 5 + r) * HIDDIM + j], W_fe2[r], f);
    f = __fadd_rn(f, b_fe2[0]);
    g_h_to[0][b * HIDDIM + j] = f;
    g_h_ti[0][b * HIDDIM + j] = f;
    g_c_to[b * HIDDIM + j] = 0.f;
    g_c_ti[b * HIDDIM + j] = 0.f;
    if (j < 8) g_inp[b * 8 + j] = 0.f;
    if (j < NBLOCK) {
        g_mto[b * NBLOCK + j] = (to_t[((size_t)b * NBLOCK + j) * 5] != -1.0f);
        g_mti[b * NBLOCK + j] = (ti_t[((size_t)b * NBLOCK + j) * 5] != -1.0f);
    }
    for (int i = j; i < NSLOT; i += HIDDIM) {
        const float* sl = slot_info + ((size_t)b * NSLOT + i) * 5;
        g_sl0 [(size_t)b * NSLOT + i] = sl[0];
        g_sw0 [(size_t)b * NSLOT + i] = sl[1];
        g_scnt[(size_t)b * NSLOT + i] = sl[4];
    }
}

// ---------------- warp-per-batch masked argmax + state mutation -----------------
__global__ void select_kernel(const float* __restrict__ to_t, float* __restrict__ out_act, int step)
{
    const int w = threadIdx.x >> 5, l = threadIdx.x & 31;
    const int b = blockIdx.x * 4 + w;

    float v = -3.4e38f; int bi = 0x7fffffff;
    for (int i = l; i < NBLOCK; i += 32) {
        float lv = g_mto[b * NBLOCK + i] ? g_lto[(size_t)b * NFUSE + i] : NEGV;
        if (lv > v || (lv == v && i < bi)) { v = lv; bi = i; }
    }
#pragma unroll
    for (int o = 16; o; o >>= 1) {
        float v2 = __shfl_xor_sync(0xffffffffu, v, o);
        int   i2 = __shfl_xor_sync(0xffffffffu, bi, o);
        if (v2 > v || (v2 == v && i2 < bi)) { v = v2; bi = i2; }
    }
    const int sel_b = bi;
    if (l == 0) {
        g_mto[b * NBLOCK + sel_b] = 0;
#pragma unroll
        for (int r = 0; r < 5; r++)
            g_inp[b * 8 + r] = to_t[((size_t)b * NBLOCK + sel_b) * 5 + r];
    }
    const float bl0 = to_t[((size_t)b * NBLOCK + sel_b) * 5 + 0];
    const float bl1 = to_t[((size_t)b * NBLOCK + sel_b) * 5 + 1];

    v = -3.4e38f; bi = 0x7fffffff;
    for (int i = l; i < NSLOT; i += 32) {
        float l0 = g_sl0[(size_t)b * NSLOT + i];
        float w0 = g_sw0[(size_t)b * NSLOT + i];
        bool bad = (bl0 >= l0) || (bl1 >= w0) || (l0 == 0.0f);
        float lv = bad ? NEGV : g_lto[(size_t)b * NFUSE + NBLOCK + i];
        if (lv > v || (lv == v && i < bi)) { v = lv; bi = i; }
    }
#pragma unroll
    for (int o = 16; o; o >>= 1) {
        float v2 = __shfl_xor_sync(0xffffffffu, v, o);
        int   i2 = __shfl_xor_sync(0xffffffffu, bi, o);
        if (v2 > v || (v2 == v && i2 < bi)) { v = v2; bi = i2; }
    }
    const int sel_s = bi;
    if (l == 0) {
        size_t si = (size_t)b * NSLOT + sel_s;
        float cnt = __fadd_rn(g_scnt[si], -1.0f);
        g_scnt[si] = cnt;
        if (cnt == 0.0f) { g_sl0[si] = 0.f; g_sw0[si] = 0.f; }
    }

    v = -3.4e38f; bi = 0x7fffffff;
    for (int i = l; i < NBLOCK; i += 32) {
        float lv = g_mti[b * NBLOCK + i] ? g_lti[(size_t)b * NBLOCK + i] : NEGV;
        if (lv > v || (lv == v && i < bi)) { v = lv; bi = i; }
    }
#pragma unroll
    for (int o = 16; o; o >>= 1) {
        float v2 = __shfl_xor_sync(0xffffffffu, v, o);
        int   i2 = __shfl_xor_sync(0xffffffffu, bi, o);
        if (v2 > v || (v2 == v && i2 < bi)) { v = v2; bi = i2; }
    }
    if (l == 0) {
        g_mti[b * NBLOCK + bi] = 0;
        float* oa = out_act + ((size_t)b * NSTEPS + step) * 3;
        oa[0] = (float)sel_b;
        oa[1] = (float)sel_s;
        oa[2] = (float)bi;
    }
}

// ---------------- launch ----------------
extern "C" void kernel_launch(void* const* d_in, const int* in_sizes, int n_in,
                              void* d_out, int out_size)
{
    const float* to_t    = (const float*)d_in[0];
    const float* ti_t    = (const float*)d_in[1];
    const float* ys_t    = (const float*)d_in[2];
    const float* slot    = (const float*)d_in[3];
    const float* W1      = (const float*)d_in[4];
    const float* b1      = (const float*)d_in[5];
    const float* W2      = (const float*)d_in[6];
    const float* b2      = (const float*)d_in[7];
    const float* W3      = (const float*)d_in[8];
    const float* b3      = (const float*)d_in[9];
    const float* W_fe2   = (const float*)d_in[10];
    const float* b_fe2   = (const float*)d_in[11];
    const float* Wih_to  = (const float*)d_in[12];
    const float* Whh_to  = (const float*)d_in[13];
    const float* bih_to  = (const float*)d_in[14];
    const float* bhh_to  = (const float*)d_in[15];
    const float* Whh_ti  = (const float*)d_in[17];
    const float* bih_ti  = (const float*)d_in[18];
    const float* bhh_ti  = (const float*)d_in[19];
    const float* Wb      = (const float*)d_in[20];
    const float* bb      = (const float*)d_in[21];
    const float* Ws      = (const float*)d_in[22];
    const float* bs      = (const float*)d_in[23];

    float* out     = (float*)d_out;
    float* out_act = out + (size_t)BATCH * KST * 5;

    float *p_xT, *p_a1, *p_a2, *p_a3, *p_hto, *p_hti;
    float *p_Wg, *p_WbWs, *p_WgT, *p_WlT, *p_W1T, *p_W2T, *p_W3T;
    cudaGetSymbolAddress((void**)&p_xT,   g_xT);
    cudaGetSymbolAddress((void**)&p_a1,   g_act1);
    cudaGetSymbolAddress((void**)&p_a2,   g_act2);
    cudaGetSymbolAddress((void**)&p_a3,   g_act3);
    cudaGetSymbolAddress((void**)&p_hto,  g_h_to);
    cudaGetSymbolAddress((void**)&p_hti,  g_h_ti);
    cudaGetSymbolAddress((void**)&p_Wg,   g_Wg);
    cudaGetSymbolAddress((void**)&p_WbWs, g_WbWs);
    cudaGetSymbolAddress((void**)&p_WgT,  g_WgT);
    cudaGetSymbolAddress((void**)&p_WlT,  g_WlT);
    cudaGetSymbolAddress((void**)&p_W1T,  g_W1T);
    cudaGetSymbolAddress((void**)&p_W2T,  g_W2T);
    cudaGetSymbolAddress((void**)&p_W3T,  g_W3T);
    float* h_to_buf[2] = { p_hto, p_hto + BATCH * HIDDIM };
    float* h_ti_buf[2] = { p_hti, p_hti + BATCH * HIDDIM };

    cudaFuncSetAttribute(sgemm_d,       cudaFuncAttributeMaxDynamicSharedMemorySize, SMEM_GEMM);
    cudaFuncSetAttribute(logits_kernel, cudaFuncAttributeMaxDynamicSharedMemorySize, SMEM_GEMM);
    cudaFuncSetAttribute(gates_kernel,  cudaFuncAttributeMaxDynamicSharedMemorySize, SMEM_GATES);

    // prep
    int nprep = (BATCH * KST + 255) / 256;
    prep_kernel<<<nprep, 256>>>(to_t, ti_t, ys_t, out);
    prep_weights<<<2048, 256>>>(Whh_to, Whh_ti, bih_to, bhh_to, bih_ti, bhh_ti,
                                Wih_to, Wb, bb, Ws, bs);
    // dup-transposed weights (new conflict-free layout)
    zfill_kernel<<<(256 * 1280 + 255) / 256, 256>>>(p_WlT, 256 * 1280);
    dupT_kernel<<<2048, 256>>>(p_WgT, 4096, p_Wg, 256, 0);
    dupT_kernel<<<400, 256>>>(p_WlT, 1280, p_WbWs, 256, 0);
    dupT_kernel<<<100, 256>>>(p_WlT, 1280, Wb, 256, 512);
    dupT_kernel<<<512, 256>>>(p_W1T, 1024, W1, KST, 0);
    dupT_kernel<<<512, 256>>>(p_W2T, 1024, W2, 512, 0);
    dupT_kernel<<<256, 256>>>(p_W3T, 512, W3, 512, 0);

    // MLP
    dim3 g1(M5 / 128, 4);
    sgemm_d<<<g1, 256, SMEM_GEMM>>>(p_xT, KST, p_W1T, 1024, b1, p_a1, 512, 512, KST, 1);
    sgemm_d<<<g1, 256, SMEM_GEMM>>>(p_a1, 512, p_W2T, 1024, b2, p_a2, 512, 512, 512, 1);
    dim3 g3(M5 / 128, 2);
    sgemm_d<<<g3, 256, SMEM_GEMM>>>(p_a2, 512, p_W3T, 512, b3, p_a3, 256, 256, 512, 1);
    feat_init_kernel<<<BATCH, HIDDIM>>>(W_fe2, b_fe2, to_t, ti_t, slot);

    dim3 gg(BATCH / 128, 8);
    dim3 gl(BATCH / 128, 5);
    for (int s = 0; s < NSTEPS; s++) {
        int cur = s & 1, nxt = cur ^ 1;
        gates_kernel <<<gg, 256, SMEM_GATES>>>(h_to_buf[cur], h_ti_buf[cur], h_to_buf[nxt], h_ti_buf[nxt]);
        logits_kernel<<<gl, 256, SMEM_GEMM>>>(h_to_buf[nxt], h_ti_buf[nxt], bb);
        select_kernel<<<BATCH / 4, 128>>>(to_t, out_act, s);
    }
}